// round 2
// baseline (speedup 1.0000x reference)
#include <cuda_runtime.h>

#define NB 8
#define NS 1024
#define NE 512
#define NH 16
#define ND 32

// Scratch for projected Q/K/V, layout [b, s, e] (e = h*32 + d)
__device__ float g_Q[NB * NS * NE];
__device__ float g_K[NB * NS * NE];
__device__ float g_V[NB * NS * NE];

// ---------------------------------------------------------------------------
// Projection: Y = X @ W^T for W in {Wq, Wk, Wv}   (torch Linear convention)
// X: [8192, 512], W: [512, 512], Y: [8192, 512]
// 128x128 block tile, K-step 8, 8x8 per thread, 256 threads.
// ---------------------------------------------------------------------------
__global__ __launch_bounds__(256, 2)
void proj_kernel(const float* __restrict__ X,
                 const float* __restrict__ Wq,
                 const float* __restrict__ Wk,
                 const float* __restrict__ Wv)
{
    __shared__ float As[8][132];
    __shared__ float Bs[8][132];

    const float* W = (blockIdx.z == 0) ? Wq : (blockIdx.z == 1) ? Wk : Wv;
    float* Y       = (blockIdx.z == 0) ? g_Q : (blockIdx.z == 1) ? g_K : g_V;

    const int m0 = blockIdx.x * 128;
    const int n0 = blockIdx.y * 128;
    const int tid = threadIdx.x;
    const int tx = tid & 15, ty = tid >> 4;
    const int lr = tid >> 1;            // 0..127
    const int lc = (tid & 1) << 2;      // 0 or 4

    const float* xa = X + (size_t)(m0 + lr) * NE + lc;
    const float* wa = W + (size_t)(n0 + lr) * NE + lc;

    float acc[8][8];
#pragma unroll
    for (int r = 0; r < 8; r++)
#pragma unroll
        for (int c = 0; c < 8; c++) acc[r][c] = 0.f;

    for (int k0 = 0; k0 < NE; k0 += 8) {
        float4 a = *(const float4*)(xa + k0);
        float4 b = *(const float4*)(wa + k0);
        __syncthreads();
        As[lc + 0][lr] = a.x; As[lc + 1][lr] = a.y;
        As[lc + 2][lr] = a.z; As[lc + 3][lr] = a.w;
        Bs[lc + 0][lr] = b.x; Bs[lc + 1][lr] = b.y;
        Bs[lc + 2][lr] = b.z; Bs[lc + 3][lr] = b.w;
        __syncthreads();
#pragma unroll
        for (int kk = 0; kk < 8; kk++) {
            float ar[8], br[8];
            *(float4*)&ar[0] = *(const float4*)&As[kk][ty * 8];
            *(float4*)&ar[4] = *(const float4*)&As[kk][ty * 8 + 4];
            *(float4*)&br[0] = *(const float4*)&Bs[kk][tx * 8];
            *(float4*)&br[4] = *(const float4*)&Bs[kk][tx * 8 + 4];
#pragma unroll
            for (int r = 0; r < 8; r++)
#pragma unroll
                for (int c = 0; c < 8; c++)
                    acc[r][c] = fmaf(ar[r], br[c], acc[r][c]);
        }
    }

#pragma unroll
    for (int r = 0; r < 8; r++) {
        float* yp = Y + (size_t)(m0 + ty * 8 + r) * NE + n0 + tx * 8;
        *(float4*)yp       = make_float4(acc[r][0], acc[r][1], acc[r][2], acc[r][3]);
        *(float4*)(yp + 4) = make_float4(acc[r][4], acc[r][5], acc[r][6], acc[r][7]);
    }
}

// ---------------------------------------------------------------------------
// Fused attention with relative position bias, flash-style online softmax.
// One CTA per (b, h, 64-row q tile). S[i,j] = q_i . (k_j + Er[j-i+1023]),
// q pre-scaled by 1/sqrt(D). Loop over 16 j-tiles of 64.
// smem (dynamic): qsT[32][68], ksT[32][68], ersT[32][132], vs[64][36], Ps[64][68]
// ---------------------------------------------------------------------------
__global__ __launch_bounds__(256)
void attn_kernel(const float* __restrict__ Er, float* __restrict__ out)
{
    extern __shared__ float sm[];
    float* qsT  = sm;                    // 32*68
    float* ksT  = qsT + 32 * 68;         // 32*68
    float* ersT = ksT + 32 * 68;         // 32*132
    float* vs   = ersT + 32 * 132;       // 64*36
    float* Ps   = vs + 64 * 36;          // 64*68

    const int b  = blockIdx.z;
    const int h  = blockIdx.y;
    const int i0 = blockIdx.x * 64;
    const int tid = threadIdx.x;
    const int tx = tid & 15, ty = tid >> 4;
    const float scale = 0.17677669529663687f;  // 1/sqrt(32)

    // Load Q tile (scaled) transposed: qsT[d][i]
    {
        const float* qg = g_Q + (size_t)(b * NS + i0) * NE + h * ND;
        for (int it = tid; it < 64 * 8; it += 256) {
            int r = it >> 3, d4 = (it & 7) << 2;
            float4 qv = *(const float4*)(qg + (size_t)r * NE + d4);
            qsT[(d4 + 0) * 68 + r] = qv.x * scale;
            qsT[(d4 + 1) * 68 + r] = qv.y * scale;
            qsT[(d4 + 2) * 68 + r] = qv.z * scale;
            qsT[(d4 + 3) * 68 + r] = qv.w * scale;
        }
    }

    float m[4], l[4], o[4][2];
#pragma unroll
    for (int r = 0; r < 4; r++) { m[r] = -1e30f; l[r] = 0.f; o[r][0] = 0.f; o[r][1] = 0.f; }

    const int erbase = 4 * (tx - ty) + 60;   // in [0, 120]

    for (int jt = 0; jt < 16; jt++) {
        const int j0 = jt * 64;
        __syncthreads();   // prior iteration done reading ks/vs/ers/Ps

        // Load K (transposed) and V (row-major) tiles
        const float* kg = g_K + (size_t)(b * NS + j0) * NE + h * ND;
        const float* vg = g_V + (size_t)(b * NS + j0) * NE + h * ND;
        for (int it = tid; it < 64 * 8; it += 256) {
            int r = it >> 3, d4 = (it & 7) << 2;
            float4 kv = *(const float4*)(kg + (size_t)r * NE + d4);
            ksT[(d4 + 0) * 68 + r] = kv.x;
            ksT[(d4 + 1) * 68 + r] = kv.y;
            ksT[(d4 + 2) * 68 + r] = kv.z;
            ksT[(d4 + 3) * 68 + r] = kv.w;
            float4 vv = *(const float4*)(vg + (size_t)r * NE + d4);
            *(float4*)&vs[r * 36 + d4] = vv;
        }
        // Er slice rows [s0, s0+126], transposed: ersT[d][t]; t in [0,127)
        const int s0 = j0 - i0 + 960;    // guaranteed in [0, 1920]
        for (int it = tid; it < 127 * 8; it += 256) {
            int t = it >> 3, d4 = (it & 7) << 2;
            float4 ev = *(const float4*)(Er + (size_t)(s0 + t) * ND + d4);
            ersT[(d4 + 0) * 132 + t] = ev.x;
            ersT[(d4 + 1) * 132 + t] = ev.y;
            ersT[(d4 + 2) * 132 + t] = ev.z;
            ersT[(d4 + 3) * 132 + t] = ev.w;
        }
        __syncthreads();

        // Scores: acc[r][c] = sum_d q * (k + er)
        float acc[4][4];
#pragma unroll
        for (int r = 0; r < 4; r++)
#pragma unroll
            for (int c = 0; c < 4; c++) acc[r][c] = 0.f;

#pragma unroll 8
        for (int d = 0; d < 32; d++) {
            float qa[4], ka[4], ev[8];
            *(float4*)&qa[0] = *(const float4*)&qsT[d * 68 + ty * 4];
            *(float4*)&ka[0] = *(const float4*)&ksT[d * 68 + tx * 4];
            *(float4*)&ev[0] = *(const float4*)&ersT[d * 132 + erbase];
            *(float4*)&ev[4] = *(const float4*)&ersT[d * 132 + erbase + 4];
#pragma unroll
            for (int r = 0; r < 4; r++)
#pragma unroll
                for (int c = 0; c < 4; c++)
                    acc[r][c] = fmaf(qa[r], ka[c] + ev[c - r + 3], acc[r][c]);
        }

        // Online softmax (row reductions across the 16 tx lanes)
#pragma unroll
        for (int r = 0; r < 4; r++) {
            float tmax = fmaxf(fmaxf(acc[r][0], acc[r][1]), fmaxf(acc[r][2], acc[r][3]));
#pragma unroll
            for (int off = 8; off >= 1; off >>= 1)
                tmax = fmaxf(tmax, __shfl_xor_sync(0xffffffffu, tmax, off));
            float mn = fmaxf(m[r], tmax);
            float corr = __expf(m[r] - mn);
            float p0 = __expf(acc[r][0] - mn);
            float p1 = __expf(acc[r][1] - mn);
            float p2 = __expf(acc[r][2] - mn);
            float p3 = __expf(acc[r][3] - mn);
            float ps = (p0 + p1) + (p2 + p3);
#pragma unroll
            for (int off = 8; off >= 1; off >>= 1)
                ps += __shfl_xor_sync(0xffffffffu, ps, off);
            l[r] = l[r] * corr + ps;
            m[r] = mn;
            o[r][0] *= corr;
            o[r][1] *= corr;
            *(float4*)&Ps[(ty * 4 + r) * 68 + tx * 4] = make_float4(p0, p1, p2, p3);
        }
        __syncthreads();

        // O += P @ V  (thread owns rows ty*4+r, dims d = tx*2 + {0,1})
#pragma unroll 4
        for (int j = 0; j < 64; j += 4) {
            float pm[4][4];
#pragma unroll
            for (int r = 0; r < 4; r++)
                *(float4*)&pm[r][0] = *(const float4*)&Ps[(ty * 4 + r) * 68 + j];
            float va[4][2];
#pragma unroll
            for (int u = 0; u < 4; u++)
                *(float2*)&va[u][0] = *(const float2*)&vs[(j + u) * 36 + tx * 2];
#pragma unroll
            for (int r = 0; r < 4; r++)
#pragma unroll
                for (int u = 0; u < 4; u++) {
                    o[r][0] = fmaf(pm[r][u], va[u][0], o[r][0]);
                    o[r][1] = fmaf(pm[r][u], va[u][1], o[r][1]);
                }
        }
    }

#pragma unroll
    for (int r = 0; r < 4; r++) {
        float inv = 1.0f / l[r];
        size_t oidx = (size_t)(b * NS + i0 + ty * 4 + r) * NE + h * ND + tx * 2;
        out[oidx]     = o[r][0] * inv;
        out[oidx + 1] = o[r][1] * inv;
    }
}

// ---------------------------------------------------------------------------
extern "C" void kernel_launch(void* const* d_in, const int* in_sizes, int n_in,
                              void* d_out, int out_size)
{
    const float* x  = (const float*)d_in[0];
    const float* Wq = (const float*)d_in[1];
    const float* Wk = (const float*)d_in[2];
    const float* Wv = (const float*)d_in[3];
    const float* Er = (const float*)d_in[4];
    float* out = (float*)d_out;

    dim3 gp(64, 4, 3);             // 8192/128, 512/128, {Q,K,V}
    proj_kernel<<<gp, 256>>>(x, Wq, Wk, Wv);

    const int smem = (32 * 68 * 2 + 32 * 132 + 64 * 36 + 64 * 68) * (int)sizeof(float); // 60928 B
    cudaFuncSetAttribute(attn_kernel, cudaFuncAttributeMaxDynamicSharedMemorySize, smem);
    dim3 ga(16, 16, 8);            // 1024/64 q-tiles, H, B
    attn_kernel<<<ga, 256, smem>>>(Er, out);
}

// round 3
// speedup vs baseline: 1.2877x; 1.2877x over previous
#include <cuda_runtime.h>

#define NB 8
#define NS 1024
#define NE 512
#define NH 16
#define ND 32

typedef unsigned long long ull;

// Scratch for projected Q/K/V, layout [b, s, e] (e = h*32 + d)
__device__ float g_Q[NB * NS * NE];
__device__ float g_K[NB * NS * NE];
__device__ float g_V[NB * NS * NE];

// ---- packed fp32x2 helpers (sm_100+ PTX) ----------------------------------
__device__ __forceinline__ ull pack2(float x, float y) {
    ull d; asm("mov.b64 %0, {%1, %2};" : "=l"(d) : "f"(x), "f"(y)); return d;
}
__device__ __forceinline__ void unpack2(ull d, float& x, float& y) {
    asm("mov.b64 {%0, %1}, %2;" : "=f"(x), "=f"(y) : "l"(d));
}
__device__ __forceinline__ void fma2(ull& d, ull a, ull b) {
    asm("fma.rn.f32x2 %0, %1, %2, %0;" : "+l"(d) : "l"(a), "l"(b));
}

// ---------------------------------------------------------------------------
// Projection: Y = X @ W^T for W in {Wq, Wk, Wv}   (torch Linear convention)
// X: [8192, 512], W: [512, 512], Y: [8192, 512]
// 128x128 block tile, K-step 8, 8x8 per thread via packed f32x2 FMA.
// ---------------------------------------------------------------------------
__global__ __launch_bounds__(256, 2)
void proj_kernel(const float* __restrict__ X,
                 const float* __restrict__ Wq,
                 const float* __restrict__ Wk,
                 const float* __restrict__ Wv)
{
    __shared__ __align__(16) float As[8][132];
    __shared__ __align__(16) float Bs[8][132];

    const float* W = (blockIdx.z == 0) ? Wq : (blockIdx.z == 1) ? Wk : Wv;
    float* Y       = (blockIdx.z == 0) ? g_Q : (blockIdx.z == 1) ? g_K : g_V;

    const int m0 = blockIdx.x * 128;
    const int n0 = blockIdx.y * 128;
    const int tid = threadIdx.x;
    const int tx = tid & 15, ty = tid >> 4;
    const int lr = tid >> 1;            // 0..127
    const int lc = (tid & 1) << 2;      // 0 or 4

    const float* xa = X + (size_t)(m0 + lr) * NE + lc;
    const float* wa = W + (size_t)(n0 + lr) * NE + lc;

    ull acc2[8][4];
#pragma unroll
    for (int r = 0; r < 8; r++)
#pragma unroll
        for (int j = 0; j < 4; j++) acc2[r][j] = 0ull;

    for (int k0 = 0; k0 < NE; k0 += 8) {
        float4 a = *(const float4*)(xa + k0);
        float4 b = *(const float4*)(wa + k0);
        __syncthreads();
        As[lc + 0][lr] = a.x; As[lc + 1][lr] = a.y;
        As[lc + 2][lr] = a.z; As[lc + 3][lr] = a.w;
        Bs[lc + 0][lr] = b.x; Bs[lc + 1][lr] = b.y;
        Bs[lc + 2][lr] = b.z; Bs[lc + 3][lr] = b.w;
        __syncthreads();
#pragma unroll
        for (int kk = 0; kk < 8; kk++) {
            float ar[8];
            *(float4*)&ar[0] = *(const float4*)&As[kk][ty * 8];
            *(float4*)&ar[4] = *(const float4*)&As[kk][ty * 8 + 4];
            ull b2[4];
#pragma unroll
            for (int j = 0; j < 4; j++)
                b2[j] = *(const ull*)&Bs[kk][tx * 8 + 2 * j];
            ull a2[8];
#pragma unroll
            for (int r = 0; r < 8; r++) a2[r] = pack2(ar[r], ar[r]);
#pragma unroll
            for (int r = 0; r < 8; r++)
#pragma unroll
                for (int j = 0; j < 4; j++)
                    fma2(acc2[r][j], a2[r], b2[j]);
        }
    }

#pragma unroll
    for (int r = 0; r < 8; r++) {
        float c[8];
#pragma unroll
        for (int j = 0; j < 4; j++) unpack2(acc2[r][j], c[2 * j], c[2 * j + 1]);
        float* yp = Y + (size_t)(m0 + ty * 8 + r) * NE + n0 + tx * 8;
        *(float4*)yp       = make_float4(c[0], c[1], c[2], c[3]);
        *(float4*)(yp + 4) = make_float4(c[4], c[5], c[6], c[7]);
    }
}

// ---------------------------------------------------------------------------
// Fused attention with relative position bias, flash-style online softmax.
// One CTA per (b, h, 128-row q tile). S[i,j] = q_i . (k_j + Er[j-i+1023]),
// q pre-scaled by 1/sqrt(D). Loop over 16 j-tiles of 64. Thread tile 8x4.
// smem: qsT[32][132], ksT[32][68], ersT[32][196], vs[64][36], Ps[128][68]
// ---------------------------------------------------------------------------
__global__ __launch_bounds__(256, 2)
void attn_kernel(const float* __restrict__ Er, float* __restrict__ out)
{
    extern __shared__ float sm[];
    float* qsT  = sm;                     // 32*132
    float* ksT  = qsT + 32 * 132;         // 32*68
    float* ersT = ksT + 32 * 68;          // 32*196
    float* vs   = ersT + 32 * 196;        // 64*36
    float* Ps   = vs + 64 * 36;           // 128*68

    const int b  = blockIdx.z;
    const int h  = blockIdx.y;
    const int i0 = blockIdx.x * 128;
    const int tid = threadIdx.x;
    const int tx = tid & 15, ty = tid >> 4;
    const float scale = 0.17677669529663687f;  // 1/sqrt(32)

    // Load Q tile (scaled) transposed: qsT[d][i], i = 0..127
    {
        const float* qg = g_Q + (size_t)(b * NS + i0) * NE + h * ND;
        for (int it = tid; it < 128 * 8; it += 256) {
            int r = it >> 3, d4 = (it & 7) << 2;
            float4 qv = *(const float4*)(qg + (size_t)r * NE + d4);
            qsT[(d4 + 0) * 132 + r] = qv.x * scale;
            qsT[(d4 + 1) * 132 + r] = qv.y * scale;
            qsT[(d4 + 2) * 132 + r] = qv.z * scale;
            qsT[(d4 + 3) * 132 + r] = qv.w * scale;
        }
    }

    float m[8], l[8], o[8][2];
#pragma unroll
    for (int r = 0; r < 8; r++) { m[r] = -1e30f; l[r] = 0.f; o[r][0] = 0.f; o[r][1] = 0.f; }

    // per-thread Er window base: t = ebase + (c - r + 7), c-r+7 in [0,10]
    const int ebase = 4 * tx - 8 * ty + 120;   // in [0, 180]

    for (int jt = 0; jt < 16; jt++) {
        const int j0 = jt * 64;
        __syncthreads();   // prior iteration done reading ks/vs/ers/Ps

        // Load K (transposed) and V (row-major) tiles
        const float* kg = g_K + (size_t)(b * NS + j0) * NE + h * ND;
        const float* vg = g_V + (size_t)(b * NS + j0) * NE + h * ND;
        for (int it = tid; it < 64 * 8; it += 256) {
            int r = it >> 3, d4 = (it & 7) << 2;
            float4 kv = *(const float4*)(kg + (size_t)r * NE + d4);
            ksT[(d4 + 0) * 68 + r] = kv.x;
            ksT[(d4 + 1) * 68 + r] = kv.y;
            ksT[(d4 + 2) * 68 + r] = kv.z;
            ksT[(d4 + 3) * 68 + r] = kv.w;
            float4 vv = *(const float4*)(vg + (size_t)r * NE + d4);
            *(float4*)&vs[r * 36 + d4] = vv;
        }
        // Er slice rows [s0, s0+190], transposed: ersT[d][t]
        // rel = j - i + 1023 = s0 + t, s0 = j0 - i0 + 896 in [0, 1856]
        const int s0 = j0 - i0 + 896;
        for (int it = tid; it < 191 * 8; it += 256) {
            int t = it >> 3, d4 = (it & 7) << 2;
            float4 ev = *(const float4*)(Er + (size_t)(s0 + t) * ND + d4);
            ersT[(d4 + 0) * 196 + t] = ev.x;
            ersT[(d4 + 1) * 196 + t] = ev.y;
            ersT[(d4 + 2) * 196 + t] = ev.z;
            ersT[(d4 + 3) * 196 + t] = ev.w;
        }
        __syncthreads();

        // Scores: acc[r][c] = sum_d q * (k + er), rows ty*8+r, cols tx*4+c
        float acc[8][4];
#pragma unroll
        for (int r = 0; r < 8; r++)
#pragma unroll
            for (int c = 0; c < 4; c++) acc[r][c] = 0.f;

#pragma unroll 4
        for (int d = 0; d < 32; d++) {
            float qa[8], ka[4], ev[12];
            *(float4*)&qa[0] = *(const float4*)&qsT[d * 132 + ty * 8];
            *(float4*)&qa[4] = *(const float4*)&qsT[d * 132 + ty * 8 + 4];
            *(float4*)&ka[0] = *(const float4*)&ksT[d * 68 + tx * 4];
            *(float4*)&ev[0] = *(const float4*)&ersT[d * 196 + ebase];
            *(float4*)&ev[4] = *(const float4*)&ersT[d * 196 + ebase + 4];
            *(float4*)&ev[8] = *(const float4*)&ersT[d * 196 + ebase + 8];
#pragma unroll
            for (int r = 0; r < 8; r++)
#pragma unroll
                for (int c = 0; c < 4; c++)
                    acc[r][c] = fmaf(qa[r], ka[c] + ev[c - r + 7], acc[r][c]);
        }

        // Online softmax (row reductions across the 16 tx lanes)
#pragma unroll
        for (int r = 0; r < 8; r++) {
            float tmax = fmaxf(fmaxf(acc[r][0], acc[r][1]), fmaxf(acc[r][2], acc[r][3]));
#pragma unroll
            for (int off = 8; off >= 1; off >>= 1)
                tmax = fmaxf(tmax, __shfl_xor_sync(0xffffffffu, tmax, off));
            float mn = fmaxf(m[r], tmax);
            float corr = __expf(m[r] - mn);
            float p0 = __expf(acc[r][0] - mn);
            float p1 = __expf(acc[r][1] - mn);
            float p2 = __expf(acc[r][2] - mn);
            float p3 = __expf(acc[r][3] - mn);
            float ps = (p0 + p1) + (p2 + p3);
#pragma unroll
            for (int off = 8; off >= 1; off >>= 1)
                ps += __shfl_xor_sync(0xffffffffu, ps, off);
            l[r] = l[r] * corr + ps;
            m[r] = mn;
            o[r][0] *= corr;
            o[r][1] *= corr;
            *(float4*)&Ps[(ty * 8 + r) * 68 + tx * 4] = make_float4(p0, p1, p2, p3);
        }
        __syncthreads();

        // O += P @ V  (thread owns rows ty*8+r, dims d = tx*2 + {0,1})
#pragma unroll 2
        for (int j = 0; j < 64; j += 4) {
            float va[4][2];
#pragma unroll
            for (int u = 0; u < 4; u++)
                *(float2*)&va[u][0] = *(const float2*)&vs[(j + u) * 36 + tx * 2];
#pragma unroll
            for (int r = 0; r < 8; r++) {
                float4 pm = *(const float4*)&Ps[(ty * 8 + r) * 68 + j];
                o[r][0] = fmaf(pm.x, va[0][0], o[r][0]);
                o[r][1] = fmaf(pm.x, va[0][1], o[r][1]);
                o[r][0] = fmaf(pm.y, va[1][0], o[r][0]);
                o[r][1] = fmaf(pm.y, va[1][1], o[r][1]);
                o[r][0] = fmaf(pm.z, va[2][0], o[r][0]);
                o[r][1] = fmaf(pm.z, va[2][1], o[r][1]);
                o[r][0] = fmaf(pm.w, va[3][0], o[r][0]);
                o[r][1] = fmaf(pm.w, va[3][1], o[r][1]);
            }
        }
    }

#pragma unroll
    for (int r = 0; r < 8; r++) {
        float inv = 1.0f / l[r];
        size_t oidx = (size_t)(b * NS + i0 + ty * 8 + r) * NE + h * ND + tx * 2;
        out[oidx]     = o[r][0] * inv;
        out[oidx + 1] = o[r][1] * inv;
    }
}

// ---------------------------------------------------------------------------
extern "C" void kernel_launch(void* const* d_in, const int* in_sizes, int n_in,
                              void* d_out, int out_size)
{
    const float* x  = (const float*)d_in[0];
    const float* Wq = (const float*)d_in[1];
    const float* Wk = (const float*)d_in[2];
    const float* Wv = (const float*)d_in[3];
    const float* Er = (const float*)d_in[4];
    float* out = (float*)d_out;

    dim3 gp(64, 4, 3);             // 8192/128, 512/128, {Q,K,V}
    proj_kernel<<<gp, 256>>>(x, Wq, Wk, Wv);

    const int smem = (32 * 132 + 32 * 68 + 32 * 196 + 64 * 36 + 128 * 68) * (int)sizeof(float); // 94720 B
    cudaFuncSetAttribute(attn_kernel, cudaFuncAttributeMaxDynamicSharedMemorySize, smem);
    dim3 ga(8, 16, 8);             // 1024/128 q-tiles, H, B
    attn_kernel<<<ga, 256, smem>>>(Er, out);
}